// round 1
// baseline (speedup 1.0000x reference)
#include <cuda_runtime.h>

#define B_ 16
#define L_ 256
#define W_ 4
#define N_ 259          // L + W - 1
#define H_ 128
#define EPS_ 1e-6f
#define BN_ (B_ * N_)   // 4144

// Scratch (no allocations allowed): norms, per-ktile partial row sums, final sums.
__device__ float g_norm[2 * BN_];          // [x1 rows | x2 rows]
__device__ float g_part[32 * 5 * 320];     // [side*16+b][kt][q(padded to 320)]
__device__ float g_asum[2 * BN_];          // [x1_a | x2_a]

// ---------------------------------------------------------------------------
// 1) Row norms: one warp per (tensor, b, n) row of 128 floats.
// ---------------------------------------------------------------------------
__global__ void norms_kernel(const float* __restrict__ x1,
                             const float* __restrict__ x2) {
    int gt   = blockIdx.x * blockDim.x + threadIdx.x;
    int warp = gt >> 5;
    int lane = gt & 31;
    if (warp >= 2 * BN_) return;
    const float* x = (warp < BN_) ? x1 : x2;
    int row = (warp < BN_) ? warp : warp - BN_;
    float4 v = reinterpret_cast<const float4*>(x + (size_t)row * H_)[lane];
    float s = v.x * v.x + v.y * v.y + v.z * v.z + v.w * v.w;
#pragma unroll
    for (int o = 16; o > 0; o >>= 1) s += __shfl_xor_sync(0xffffffffu, s, o);
    if (lane == 0) g_norm[warp] = s;
}

// ---------------------------------------------------------------------------
// 2) Attention partial row sums. Block = (qtile, ktile, side*16+b).
//    Computes dots of a 64q x 64k tile via smem-transposed operands and a
//    4x4 register tile, then att = 1/(1+sqrt(nq+nk-2dot+eps)), sums over the
//    tile's keys per query, writes one partial per (block-row, ktile).
// ---------------------------------------------------------------------------
__global__ void __launch_bounds__(256) attn_partial(const float* __restrict__ x1,
                                                    const float* __restrict__ x2) {
    int qt = blockIdx.x;            // 0..4
    int kt = blockIdx.y;            // 0..4
    int bs = blockIdx.z;            // 0..31
    int b = bs & 15;
    int s = bs >> 4;                // 0: Q=x1 -> x1_a ; 1: Q=x2 -> x2_a

    const float* Qg = (s ? x2 : x1) + (size_t)b * N_ * H_;
    const float* Kg = (s ? x1 : x2) + (size_t)b * N_ * H_;
    const float* nQ = g_norm + (s ? BN_ : 0) + b * N_;
    const float* nK = g_norm + (s ? 0 : BN_) + b * N_;

    // Transposed tiles: [h within 64-chunk][row], stride 68 floats (16B aligned,
    // conflict-free vectorized loads on the compute path).
    __shared__ float Qs[64][68];
    __shared__ float Ks[64][68];

    int tid = threadIdx.x;
    int tx = tid & 15;              // key group
    int ty = tid >> 4;              // query group
    int q0 = qt * 64;
    int k0 = kt * 64;

    float acc[4][4];
#pragma unroll
    for (int r = 0; r < 4; r++)
#pragma unroll
        for (int c = 0; c < 4; c++) acc[r][c] = 0.0f;

    for (int hc = 0; hc < H_; hc += 64) {
        __syncthreads();
        int rot = tid & 3;
        // Stage Q tile (coalesced gmem float4, lane-rotated transpose scatter)
#pragma unroll
        for (int i = tid; i < 1024; i += 256) {
            int r  = i >> 4;        // row within tile
            int c4 = i & 15;        // which float4 along h
            float4 v = make_float4(0.f, 0.f, 0.f, 0.f);
            int q = q0 + r;
            if (q < N_)
                v = *reinterpret_cast<const float4*>(Qg + (size_t)q * H_ + hc + c4 * 4);
            float vv[4] = {v.x, v.y, v.z, v.w};
#pragma unroll
            for (int jj = 0; jj < 4; jj++) {
                int j = (jj + rot) & 3;
                Qs[c4 * 4 + j][r] = vv[j];
            }
        }
        // Stage K tile
#pragma unroll
        for (int i = tid; i < 1024; i += 256) {
            int r  = i >> 4;
            int c4 = i & 15;
            float4 v = make_float4(0.f, 0.f, 0.f, 0.f);
            int k = k0 + r;
            if (k < N_)
                v = *reinterpret_cast<const float4*>(Kg + (size_t)k * H_ + hc + c4 * 4);
            float vv[4] = {v.x, v.y, v.z, v.w};
#pragma unroll
            for (int jj = 0; jj < 4; jj++) {
                int j = (jj + rot) & 3;
                Ks[c4 * 4 + j][r] = vv[j];
            }
        }
        __syncthreads();

#pragma unroll 16
        for (int h = 0; h < 64; h++) {
            float4 qv = *reinterpret_cast<const float4*>(&Qs[h][ty * 4]);
            float4 kv = *reinterpret_cast<const float4*>(&Ks[h][tx * 4]);
            acc[0][0] = fmaf(qv.x, kv.x, acc[0][0]);
            acc[0][1] = fmaf(qv.x, kv.y, acc[0][1]);
            acc[0][2] = fmaf(qv.x, kv.z, acc[0][2]);
            acc[0][3] = fmaf(qv.x, kv.w, acc[0][3]);
            acc[1][0] = fmaf(qv.y, kv.x, acc[1][0]);
            acc[1][1] = fmaf(qv.y, kv.y, acc[1][1]);
            acc[1][2] = fmaf(qv.y, kv.z, acc[1][2]);
            acc[1][3] = fmaf(qv.y, kv.w, acc[1][3]);
            acc[2][0] = fmaf(qv.z, kv.x, acc[2][0]);
            acc[2][1] = fmaf(qv.z, kv.y, acc[2][1]);
            acc[2][2] = fmaf(qv.z, kv.z, acc[2][2]);
            acc[2][3] = fmaf(qv.z, kv.w, acc[2][3]);
            acc[3][0] = fmaf(qv.w, kv.x, acc[3][0]);
            acc[3][1] = fmaf(qv.w, kv.y, acc[3][1]);
            acc[3][2] = fmaf(qv.w, kv.z, acc[3][2]);
            acc[3][3] = fmaf(qv.w, kv.w, acc[3][3]);
        }
    }

    // Epilogue: attention + per-query sum over this block's keys.
    float nk[4];
#pragma unroll
    for (int c = 0; c < 4; c++) {
        int k = k0 + tx * 4 + c;
        nk[c] = (k < N_) ? nK[k] : 0.0f;
    }
#pragma unroll
    for (int r = 0; r < 4; r++) {
        int q = q0 + ty * 4 + r;
        float sum = 0.0f;
        if (q < N_) {
            float nq = nQ[q];
#pragma unroll
            for (int c = 0; c < 4; c++) {
                int k = k0 + tx * 4 + c;
                if (k < N_) {
                    float d2 = fmaxf(nq + nk[c] - 2.0f * acc[r][c], 0.0f) + EPS_;
                    float e  = sqrtf(d2);
                    sum += __fdividef(1.0f, 1.0f + e);
                }
            }
        }
        // reduce across the 16 tx lanes (stays within each half-warp)
#pragma unroll
        for (int o = 1; o < 16; o <<= 1) sum += __shfl_xor_sync(0xffffffffu, sum, o);
        if (tx == 0 && q < N_)
            g_part[(bs * 5 + kt) * 320 + q0 + ty * 4 + r] = sum;
    }
}

// ---------------------------------------------------------------------------
// 3) Reduce the 5 ktile partials per (side, b, q).
// ---------------------------------------------------------------------------
__global__ void reduce_partials_kernel() {
    int i = blockIdx.x * blockDim.x + threadIdx.x;
    if (i >= 2 * BN_) return;
    int s   = i / BN_;
    int rem = i - s * BN_;
    int b   = rem / N_;
    int q   = rem - b * N_;
    int bs  = s * 16 + b;
    float sum = 0.0f;
#pragma unroll
    for (int kt = 0; kt < 5; kt++) sum += g_part[(bs * 5 + kt) * 320 + q];
    g_asum[i] = sum;
}

// ---------------------------------------------------------------------------
// 4) Windowed weighted-sum epilogue:
//    out_w[b,l,h] = sum_{k=0..3} x_w[b,l+k,h] * a_w[b,l+k]
// ---------------------------------------------------------------------------
__global__ void wp_kernel(const float* __restrict__ x1,
                          const float* __restrict__ x2,
                          float* __restrict__ out) {
    int i = blockIdx.x * blockDim.x + threadIdx.x;   // over (which,b,l,h4)
    if (i >= 2 * B_ * L_ * (H_ / 4)) return;
    int h4 = i & 31;
    int l  = (i >> 5) & 255;
    int b  = (i >> 13) & 15;
    int w  = i >> 17;
    const float* x = (w ? x2 : x1) + (size_t)b * N_ * H_;
    const float* a = g_asum + w * BN_ + b * N_;
    float4 o = make_float4(0.f, 0.f, 0.f, 0.f);
#pragma unroll
    for (int k = 0; k < W_; k++) {
        float4 v = *reinterpret_cast<const float4*>(x + (size_t)(l + k) * H_ + h4 * 4);
        float wg = a[l + k];
        o.x = fmaf(v.x, wg, o.x);
        o.y = fmaf(v.y, wg, o.y);
        o.z = fmaf(v.z, wg, o.z);
        o.w = fmaf(v.w, wg, o.w);
    }
    reinterpret_cast<float4*>(out)[i] = o;
}

// ---------------------------------------------------------------------------
extern "C" void kernel_launch(void* const* d_in, const int* in_sizes, int n_in,
                              void* d_out, int out_size) {
    const float* x1 = (const float*)d_in[0];
    const float* x2 = (const float*)d_in[1];
    float* out = (float*)d_out;

    norms_kernel<<<(2 * BN_ * 32 + 255) / 256, 256>>>(x1, x2);

    dim3 grid(5, 5, 32);
    attn_partial<<<grid, 256>>>(x1, x2);

    reduce_partials_kernel<<<(2 * BN_ + 255) / 256, 256>>>();

    wp_kernel<<<(2 * B_ * L_ * 32 + 255) / 256, 256>>>(x1, x2, out);
}

// round 2
// speedup vs baseline: 1.5685x; 1.5685x over previous
#include <cuda_runtime.h>

#define B_ 16
#define L_ 256
#define W_ 4
#define N_ 259          // L + W - 1
#define H_ 128
#define EPS_ 1e-6f
#define BN_ (B_ * N_)   // 4144

// Scratch (no allocations allowed).
__device__ float g_norm[2 * BN_];        // [x1 rows | x2 rows]
__device__ float g_p1[16 * 5 * 320];     // x1_a partials: [b][it][j padded]
__device__ float g_p2[16 * 5 * 320];     // x2_a partials: [b][jt][i padded]
__device__ float g_asum[2 * BN_];        // [x1_a | x2_a]

// ---------------------------------------------------------------------------
// 1) Row norms: one warp per (tensor, b, n) row of 128 floats.
// ---------------------------------------------------------------------------
__global__ void norms_kernel(const float* __restrict__ x1,
                             const float* __restrict__ x2) {
    int gt   = blockIdx.x * blockDim.x + threadIdx.x;
    int warp = gt >> 5;
    int lane = gt & 31;
    if (warp >= 2 * BN_) return;
    const float* x = (warp < BN_) ? x1 : x2;
    int row = (warp < BN_) ? warp : warp - BN_;
    float4 v = reinterpret_cast<const float4*>(x + (size_t)row * H_)[lane];
    float s = v.x * v.x + v.y * v.y + v.z * v.z + v.w * v.w;
#pragma unroll
    for (int o = 16; o > 0; o >>= 1) s += __shfl_xor_sync(0xffffffffu, s, o);
    if (lane == 0) g_norm[warp] = s;
}

// ---------------------------------------------------------------------------
// 2) Attention tile: computes the att matrix ONCE per (i,j) tile and emits
//    BOTH marginals: per-i sums (-> x2_a partials, shfl over tx lanes) and
//    per-j sums (-> x1_a partials, smem cross-warp reduce).
//    att[b,i,j] = 1/(1+sqrt(|x2_i|^2+|x1_j|^2-2<x2_i,x1_j>+eps))
// ---------------------------------------------------------------------------
__global__ void __launch_bounds__(256) attn_tile(const float* __restrict__ x1,
                                                 const float* __restrict__ x2) {
    int it = blockIdx.x;            // i tile (x2 rows), 0..4
    int jt = blockIdx.y;            // j tile (x1 rows), 0..4
    int b  = blockIdx.z;            // 0..15

    const float* Ag = x2 + (size_t)b * N_ * H_;   // rows i
    const float* Bg = x1 + (size_t)b * N_ * H_;   // rows j
    const float* nA = g_norm + BN_ + b * N_;      // x2 norms
    const float* nB = g_norm + b * N_;            // x1 norms

    // Transposed tiles: [h within 64-chunk][row], stride 68 (16B aligned).
    __shared__ float As[64][68];
    __shared__ float Bs[64][68];

    int tid = threadIdx.x;
    int tx = tid & 15;              // j group
    int ty = tid >> 4;              // i group
    int i0 = it * 64;
    int j0 = jt * 64;

    float acc[4][4];                // [r over i][c over j]
#pragma unroll
    for (int r = 0; r < 4; r++)
#pragma unroll
        for (int c = 0; c < 4; c++) acc[r][c] = 0.0f;

    for (int hc = 0; hc < H_; hc += 64) {
        __syncthreads();
        int rot = tid & 3;
#pragma unroll
        for (int i = tid; i < 1024; i += 256) {
            int r  = i >> 4;
            int c4 = i & 15;
            float4 v = make_float4(0.f, 0.f, 0.f, 0.f);
            int row = i0 + r;
            if (row < N_)
                v = *reinterpret_cast<const float4*>(Ag + (size_t)row * H_ + hc + c4 * 4);
            float vv[4] = {v.x, v.y, v.z, v.w};
#pragma unroll
            for (int jj = 0; jj < 4; jj++) {
                int j = (jj + rot) & 3;
                As[c4 * 4 + j][r] = vv[j];
            }
        }
#pragma unroll
        for (int i = tid; i < 1024; i += 256) {
            int r  = i >> 4;
            int c4 = i & 15;
            float4 v = make_float4(0.f, 0.f, 0.f, 0.f);
            int row = j0 + r;
            if (row < N_)
                v = *reinterpret_cast<const float4*>(Bg + (size_t)row * H_ + hc + c4 * 4);
            float vv[4] = {v.x, v.y, v.z, v.w};
#pragma unroll
            for (int jj = 0; jj < 4; jj++) {
                int j = (jj + rot) & 3;
                Bs[c4 * 4 + j][r] = vv[j];
            }
        }
        __syncthreads();

#pragma unroll 16
        for (int h = 0; h < 64; h++) {
            float4 iv = *reinterpret_cast<const float4*>(&As[h][ty * 4]);
            float4 jv = *reinterpret_cast<const float4*>(&Bs[h][tx * 4]);
            acc[0][0] = fmaf(iv.x, jv.x, acc[0][0]);
            acc[0][1] = fmaf(iv.x, jv.y, acc[0][1]);
            acc[0][2] = fmaf(iv.x, jv.z, acc[0][2]);
            acc[0][3] = fmaf(iv.x, jv.w, acc[0][3]);
            acc[1][0] = fmaf(iv.y, jv.x, acc[1][0]);
            acc[1][1] = fmaf(iv.y, jv.y, acc[1][1]);
            acc[1][2] = fmaf(iv.y, jv.z, acc[1][2]);
            acc[1][3] = fmaf(iv.y, jv.w, acc[1][3]);
            acc[2][0] = fmaf(iv.z, jv.x, acc[2][0]);
            acc[2][1] = fmaf(iv.z, jv.y, acc[2][1]);
            acc[2][2] = fmaf(iv.z, jv.z, acc[2][2]);
            acc[2][3] = fmaf(iv.z, jv.w, acc[2][3]);
            acc[3][0] = fmaf(iv.w, jv.x, acc[3][0]);
            acc[3][1] = fmaf(iv.w, jv.y, acc[3][1]);
            acc[3][2] = fmaf(iv.w, jv.z, acc[3][2]);
            acc[3][3] = fmaf(iv.w, jv.w, acc[3][3]);
        }
    }

    // Epilogue: attention values + both marginals.
    float nb[4];
#pragma unroll
    for (int c = 0; c < 4; c++) {
        int j = j0 + tx * 4 + c;
        nb[c] = (j < N_) ? nB[j] : 0.0f;
    }
    float jp[4] = {0.f, 0.f, 0.f, 0.f};   // per-j (column) partials
#pragma unroll
    for (int r = 0; r < 4; r++) {
        int i = i0 + ty * 4 + r;
        float is = 0.0f;                   // per-i (row) partial
        if (i < N_) {
            float na = nA[i];
#pragma unroll
            for (int c = 0; c < 4; c++) {
                int j = j0 + tx * 4 + c;
                if (j < N_) {
                    float d2  = fmaxf(na + nb[c] - 2.0f * acc[r][c], 0.0f) + EPS_;
                    float e   = sqrtf(d2);
                    float att = __fdividef(1.0f, 1.0f + e);
                    is += att;
                    jp[c] += att;
                }
            }
        }
#pragma unroll
        for (int o = 1; o < 16; o <<= 1) is += __shfl_xor_sync(0xffffffffu, is, o);
        if (tx == 0 && i < N_)
            g_p2[(b * 5 + jt) * 320 + i] = is;
    }

    // Cross-warp reduction for per-j sums (reuse As as a [16][64] buffer).
    __syncthreads();
    float* red = &As[0][0];
    *reinterpret_cast<float4*>(red + ty * 64 + tx * 4) =
        make_float4(jp[0], jp[1], jp[2], jp[3]);
    __syncthreads();
    if (tid < 64) {
        float s = 0.0f;
#pragma unroll
        for (int t = 0; t < 16; t++) s += red[t * 64 + tid];
        int j = j0 + tid;
        if (j < N_) g_p1[(b * 5 + it) * 320 + j] = s;
    }
}

// ---------------------------------------------------------------------------
// 3) Reduce the 5 tile partials per (side, b, q).
// ---------------------------------------------------------------------------
__global__ void reduce_partials_kernel() {
    int i = blockIdx.x * blockDim.x + threadIdx.x;
    if (i >= 2 * BN_) return;
    int s   = i / BN_;
    int rem = i - s * BN_;
    int b   = rem / N_;
    int q   = rem - b * N_;
    const float* p = (s == 0) ? g_p1 : g_p2;
    float sum = 0.0f;
#pragma unroll
    for (int t = 0; t < 5; t++) sum += p[(b * 5 + t) * 320 + q];
    g_asum[i] = sum;
}

// ---------------------------------------------------------------------------
// 4) Windowed weighted-sum epilogue, sliding window: each thread emits 4
//    consecutive l outputs from 7 row loads (1.75 loads/output).
//    out_w[b,l,h] = sum_{k=0..3} x_w[b,l+k,h] * a_w[b,l+k]
// ---------------------------------------------------------------------------
__global__ void wp_kernel(const float* __restrict__ x1,
                          const float* __restrict__ x2,
                          float* __restrict__ out) {
    int i = blockIdx.x * blockDim.x + threadIdx.x;   // over (w,b,lc,h4)
    if (i >= 2 * B_ * 64 * 32) return;
    int h4 = i & 31;
    int lc = (i >> 5) & 63;
    int b  = (i >> 11) & 15;
    int w  = i >> 15;
    const float* x = (w ? x2 : x1) + (size_t)b * N_ * H_ + h4 * 4;
    const float* a = g_asum + w * BN_ + b * N_;
    int l0 = lc * 4;

    float4 wx[7];
#pragma unroll
    for (int k = 0; k < 7; k++) {
        float4 v  = *reinterpret_cast<const float4*>(x + (size_t)(l0 + k) * H_);
        float  wg = a[l0 + k];
        wx[k] = make_float4(v.x * wg, v.y * wg, v.z * wg, v.w * wg);
    }
#pragma unroll
    for (int t = 0; t < 4; t++) {
        float4 o;
        o.x = wx[t].x + wx[t + 1].x + wx[t + 2].x + wx[t + 3].x;
        o.y = wx[t].y + wx[t + 1].y + wx[t + 2].y + wx[t + 3].y;
        o.z = wx[t].z + wx[t + 1].z + wx[t + 2].z + wx[t + 3].z;
        o.w = wx[t].w + wx[t + 1].w + wx[t + 2].w + wx[t + 3].w;
        size_t oi = ((size_t)(w * 16 + b) * 256 + (l0 + t)) * 32 + h4;
        reinterpret_cast<float4*>(out)[oi] = o;
    }
}

// ---------------------------------------------------------------------------
extern "C" void kernel_launch(void* const* d_in, const int* in_sizes, int n_in,
                              void* d_out, int out_size) {
    const float* x1 = (const float*)d_in[0];
    const float* x2 = (const float*)d_in[1];
    float* out = (float*)d_out;

    norms_kernel<<<(2 * BN_ * 32 + 255) / 256, 256>>>(x1, x2);

    dim3 grid(5, 5, 16);
    attn_tile<<<grid, 256>>>(x1, x2);

    reduce_partials_kernel<<<(2 * BN_ + 255) / 256, 256>>>();

    wp_kernel<<<(2 * B_ * 64 * 32 + 255) / 256, 256>>>(x1, x2, out);
}